// round 1
// baseline (speedup 1.0000x reference)
#include <cuda_runtime.h>
#include <cstdint>

#define MAXN 50048          // 782 * 64, covers N=50000
#define IN_DIM 128
#define HEADS 4
#define OUT_DIM 64
#define FTOT 256            // HEADS*OUT_DIM

// ---------------- scratch (static device globals: allowed) ----------------
__device__ float  g_h[(size_t)MAXN * FTOT];     // 51.25 MB: h = x @ W
__device__ float4 g_asrc[MAXN];                 // per-node att logits (4 heads)
__device__ float4 g_adst[MAXN];
__device__ float4 g_s[MAXN];                    // softmax denominators
__device__ int    g_stride;                     // 1 = int32 edge_index, 2 = int64

// ---------------- helpers ----------------
__device__ __forceinline__ void red_add_f4(float* addr, float4 v) {
    asm volatile("red.global.add.v4.f32 [%0], {%1, %2, %3, %4};"
                 :: "l"(addr), "f"(v.x), "f"(v.y), "f"(v.z), "f"(v.w)
                 : "memory");
}

__device__ __forceinline__ float lrelu(float e) {
    return e > 0.0f ? e : 0.2f * e;
}

// ---------------- 0: edge dtype detection ----------------
__global__ void detect_kernel(const unsigned* __restrict__ w) {
    if (threadIdx.x == 0) {
        int is64 = 1;
        #pragma unroll 1
        for (int j = 1; j < 64; j += 2) {
            if (w[j] != 0u) { is64 = 0; break; }
        }
        g_stride = is64 ? 2 : 1;
    }
}

// ---------------- 1: zero out + s ----------------
__global__ void zero_kernel(float4* __restrict__ out4, int n_out4, int N) {
    int i = blockIdx.x * blockDim.x + threadIdx.x;
    if (i < n_out4) out4[i] = make_float4(0.f, 0.f, 0.f, 0.f);
    if (i < N)      g_s[i] = make_float4(0.f, 0.f, 0.f, 0.f);
}

// ---------------- 2: GEMM  h[N,256] = x[N,128] @ W[128,256] ----------------
// 64x64 tile per 256-thread block, K staged in two 64-chunks.
// As is k-major (transposed, pad 68) so the a-fragment is a float4.
__global__ void gemm_kernel(const float* __restrict__ x,
                            const float* __restrict__ W, int N) {
    __shared__ float As[64 * 68];
    __shared__ float Bs[64 * 64];
    const int tid = threadIdx.x;
    const int m_base = blockIdx.x * 64;
    const int n_base = blockIdx.y * 64;
    const int tx = tid & 15;
    const int ty = tid >> 4;

    float acc[4][4];
    #pragma unroll
    for (int i = 0; i < 4; i++)
        #pragma unroll
        for (int j = 0; j < 4; j++) acc[i][j] = 0.0f;

    #pragma unroll 1
    for (int kc = 0; kc < 2; kc++) {
        // load x tile transposed: As[k*68 + r] = x[m_base+r][kc*64+k]
        #pragma unroll
        for (int t = 0; t < 16; t++) {
            int idx = tid + t * 256;           // 0..4095
            int r = idx >> 6;
            int k = idx & 63;
            int row = m_base + r;
            if (row >= N) row = N - 1;         // clamp; pad rows are unused
            As[k * 68 + r] = x[row * IN_DIM + kc * 64 + k];
        }
        // load W tile: Bs[k*64 + n] = W[(kc*64+k)*256 + n_base+n]
        #pragma unroll
        for (int t = 0; t < 4; t++) {
            int q = tid + t * 256;             // float4 index 0..1023
            int k  = q >> 4;
            int nq = q & 15;
            float4 v = *(const float4*)(W + (kc * 64 + k) * FTOT + n_base + nq * 4);
            *(float4*)(Bs + k * 64 + nq * 4) = v;
        }
        __syncthreads();

        #pragma unroll
        for (int k = 0; k < 64; k++) {
            float4 a4 = *(const float4*)(As + k * 68 + ty * 4);
            float4 b4 = *(const float4*)(Bs + k * 64 + tx * 4);
            float a[4] = {a4.x, a4.y, a4.z, a4.w};
            float b[4] = {b4.x, b4.y, b4.z, b4.w};
            #pragma unroll
            for (int i = 0; i < 4; i++)
                #pragma unroll
                for (int j = 0; j < 4; j++)
                    acc[i][j] = fmaf(a[i], b[j], acc[i][j]);
        }
        __syncthreads();
    }

    #pragma unroll
    for (int i = 0; i < 4; i++) {
        float4 v = make_float4(acc[i][0], acc[i][1], acc[i][2], acc[i][3]);
        *(float4*)(g_h + (size_t)(m_base + ty * 4 + i) * FTOT + n_base + tx * 4) = v;
    }
}

// ---------------- 3: per-node attention logits ----------------
// one warp per node; lane owns 8 contiguous floats (2 float4) => one head per lane-octet
__global__ void att_kernel(const float* __restrict__ att_src,
                           const float* __restrict__ att_dst, int N) {
    int gt = blockIdx.x * blockDim.x + threadIdx.x;
    int node = gt >> 5;
    int lane = gt & 31;
    if (node >= N) return;

    const float4* hv = (const float4*)(g_h + (size_t)node * FTOT);
    const float4* as4 = (const float4*)att_src;
    const float4* ad4 = (const float4*)att_dst;

    float s1 = 0.f, s2 = 0.f;
    #pragma unroll
    for (int t = 0; t < 2; t++) {
        int q = lane * 2 + t;                  // float4 chunk 0..63
        float4 h4 = hv[q];
        float4 a4 = __ldg(&as4[q]);
        float4 d4 = __ldg(&ad4[q]);
        s1 += h4.x * a4.x + h4.y * a4.y + h4.z * a4.z + h4.w * a4.w;
        s2 += h4.x * d4.x + h4.y * d4.y + h4.z * d4.z + h4.w * d4.w;
    }
    // reduce within lane-octets (one head per 8 lanes)
    #pragma unroll
    for (int off = 4; off >= 1; off >>= 1) {
        s1 += __shfl_xor_sync(0xffffffffu, s1, off);
        s2 += __shfl_xor_sync(0xffffffffu, s2, off);
    }
    if ((lane & 7) == 0) {
        int head = lane >> 3;
        ((float*)&g_asrc[node])[head] = s1;
        ((float*)&g_adst[node])[head] = s2;
    }
}

// ---------------- 4: edge pass 1 — softmax denominators ----------------
__global__ void edge_sum_kernel(const unsigned* __restrict__ w, int E, int N) {
    int i = blockIdx.x * blockDim.x + threadIdx.x;
    int ET = E + N;
    if (i >= ET) return;
    int st = g_stride;
    int s, d;
    if (i < E) {
        s = (int)w[st * i];
        d = (int)w[st * E + st * i];
    } else {
        s = d = i - E;                         // self loop
    }
    float4 as = g_asrc[s];
    float4 ad = g_adst[d];
    float4 ex;
    ex.x = __expf(lrelu(as.x + ad.x));
    ex.y = __expf(lrelu(as.y + ad.y));
    ex.z = __expf(lrelu(as.z + ad.z));
    ex.w = __expf(lrelu(as.w + ad.w));
    red_add_f4((float*)&g_s[d], ex);
}

// ---------------- 5: edge pass 2 — aggregate messages ----------------
// one warp per edge: gather 1 KB of h[src], scale per head, red.v4 into out[dst]
__global__ void edge_agg_kernel(const unsigned* __restrict__ w,
                                float* __restrict__ out, int E, int N) {
    int gt = blockIdx.x * blockDim.x + threadIdx.x;
    int edge = gt >> 5;
    int lane = gt & 31;
    int ET = E + N;
    if (edge >= ET) return;
    int st = g_stride;
    int s, d;
    if (edge < E) {
        s = (int)w[st * edge];
        d = (int)w[st * E + st * edge];
    } else {
        s = d = edge - E;
    }
    float4 as = g_asrc[s];                     // broadcast loads within warp
    float4 ad = g_adst[d];
    float4 sv = g_s[d];
    float alphas[4];
    alphas[0] = __expf(lrelu(as.x + ad.x)) / (sv.x + 1e-16f);
    alphas[1] = __expf(lrelu(as.y + ad.y)) / (sv.y + 1e-16f);
    alphas[2] = __expf(lrelu(as.z + ad.z)) / (sv.z + 1e-16f);
    alphas[3] = __expf(lrelu(as.w + ad.w)) / (sv.w + 1e-16f);

    const float4* hrow = (const float4*)(g_h + (size_t)s * FTOT);
    float* orow = out + (size_t)d * FTOT;
    #pragma unroll
    for (int t = 0; t < 2; t++) {
        int q = lane + t * 32;                 // float4 chunk 0..63
        float4 hv = hrow[q];
        float a = alphas[q >> 4];
        float4 v = make_float4(a * hv.x, a * hv.y, a * hv.z, a * hv.w);
        red_add_f4(orow + 4 * q, v);
    }
}

// ---------------- 6: epilogue — bias + beta-mix ELU ----------------
__global__ void final_kernel(float* __restrict__ out,
                             const float* __restrict__ bias, int N) {
    int q = blockIdx.x * blockDim.x + threadIdx.x;     // float4 index
    int total = N * (FTOT / 4);
    if (q >= total) return;
    float4 z4 = ((float4*)out)[q];
    float4 b4 = __ldg(((const float4*)bias) + (q & 63));
    float z[4] = {z4.x + b4.x, z4.y + b4.y, z4.z + b4.z, z4.w + b4.w};
    float r[4];
    #pragma unroll
    for (int c = 0; c < 4; c++) {
        float zz = z[c];
        float e = zz > 0.0f ? zz : expm1f(zz);
        r[c] = 0.5f * zz + 0.5f * e;
    }
    ((float4*)out)[q] = make_float4(r[0], r[1], r[2], r[3]);
}

// ---------------- launch ----------------
extern "C" void kernel_launch(void* const* d_in, const int* in_sizes, int n_in,
                              void* d_out, int out_size) {
    const float*    x       = (const float*)d_in[0];
    const unsigned* edge    = (const unsigned*)d_in[1];
    const float*    W       = (const float*)d_in[2];
    const float*    att_src = (const float*)d_in[3];
    const float*    att_dst = (const float*)d_in[4];
    const float*    bias    = (const float*)d_in[5];
    float*          out     = (float*)d_out;

    const int N = in_sizes[0] / IN_DIM;        // 50000
    const int E = in_sizes[1] / 2;             // 800000
    const int ET = E + N;

    detect_kernel<<<1, 32>>>(edge);

    {
        int n4 = N * (FTOT / 4);
        zero_kernel<<<(n4 + 255) / 256, 256>>>((float4*)out, n4, N);
    }

    {
        dim3 grid((N + 63) / 64, FTOT / 64);
        gemm_kernel<<<grid, 256>>>(x, W, N);
    }

    att_kernel<<<((long)N * 32 + 255) / 256, 256>>>(att_src, att_dst, N);

    edge_sum_kernel<<<(ET + 255) / 256, 256>>>(edge, E, N);

    edge_agg_kernel<<<((long)ET * 32 + 255) / 256, 256>>>(edge, out, E, N);

    {
        int total = N * (FTOT / 4);
        final_kernel<<<(total + 255) / 256, 256>>>(out, bias, N);
    }
}

// round 2
// speedup vs baseline: 1.0246x; 1.0246x over previous
#include <cuda_runtime.h>
#include <cstdint>

#define MAXN 50048          // 782 * 64
#define MAXE 860032         // >= E + N
#define IN_DIM 128
#define HEADS 4
#define OUT_DIM 64
#define FTOT 256

// ---------------- scratch ----------------
__device__ float  g_h[(size_t)MAXN * FTOT];     // 51.25 MB
__device__ float4 g_asrc[MAXN];
__device__ float4 g_adst[MAXN];
__device__ float4 g_inv[MAXN];                  // 1/(sum+eps) per head
__device__ float4 g_ex[MAXE];                   // exp(logit) per sorted edge
__device__ int    g_src[MAXE];                  // CSR src, sorted by dst
__device__ int    g_cnt[MAXN];
__device__ int    g_off[MAXN + 1];
__device__ int    g_cur[MAXN];
__device__ int    g_stride;                     // 1 = int32 edges, 2 = int64

__device__ __forceinline__ float lrelu(float e) {
    return e > 0.0f ? e : 0.2f * e;
}

// ---------------- 0: edge dtype detection ----------------
__global__ void detect_kernel(const unsigned* __restrict__ w) {
    if (threadIdx.x == 0) {
        int is64 = 1;
        #pragma unroll 1
        for (int j = 1; j < 64; j += 2)
            if (w[j] != 0u) { is64 = 0; break; }
        g_stride = is64 ? 2 : 1;
    }
}

// ---------------- 1: zero degree counters ----------------
__global__ void zero_cnt_kernel(int N) {
    int i = blockIdx.x * blockDim.x + threadIdx.x;
    if (i < N) g_cnt[i] = 0;
}

// ---------------- 2: GEMM h = x @ W with packed f32x2 FMA ----------------
// 64x64 tile per 256-thread block; K staged in two 64-chunks processed as
// 32 k-pairs. SMEM tiles are (k,k+1)-interleaved so fma.rn.f32x2 accumulates
// two K steps per instruction. Att logits fused into epilogue (one head per
// blockIdx.y column).
#define AS_STRIDE 66   // float2 units per k2 row (pad keeps 16B alignment)
#define BS_STRIDE 64

__global__ void gemm_kernel(const float* __restrict__ x,
                            const float* __restrict__ W,
                            const float* __restrict__ att_src,
                            const float* __restrict__ att_dst, int N) {
    __shared__ float As[32 * AS_STRIDE * 2];    // 4224 floats
    __shared__ float Bs[32 * BS_STRIDE * 2];    // 4096 floats
    const int tid = threadIdx.x;
    const int m_base = blockIdx.x * 64;
    const int head = blockIdx.y;
    const int n_base = head * OUT_DIM;
    const int tx = tid & 15;
    const int ty = tid >> 4;

    unsigned long long acc2[4][4];
    #pragma unroll
    for (int i = 0; i < 4; i++)
        #pragma unroll
        for (int j = 0; j < 4; j++) acc2[i][j] = 0ULL;

    #pragma unroll 1
    for (int kc = 0; kc < 2; kc++) {
        // As fill: As_pair[k2][r] = (x[row][2k2], x[row][2k2+1])
        #pragma unroll
        for (int t = 0; t < 8; t++) {
            int idx = tid + t * 256;            // 0..2047
            int r = idx >> 5;
            int k2 = idx & 31;
            int row = m_base + r;
            if (row >= N) row = N - 1;
            float2 v = *(const float2*)(x + row * IN_DIM + kc * 64 + k2 * 2);
            *(float2*)(As + (k2 * AS_STRIDE + r) * 2) = v;
        }
        // Bs fill: Bs_pair[k2][n] = (W[2k2][n], W[2k2+1][n])
        #pragma unroll
        for (int t = 0; t < 4; t++) {
            int q = tid + t * 256;              // 0..1023 float4s
            int kk = q >> 4;
            int nq = q & 15;
            float4 v = *(const float4*)(W + (kc * 64 + kk) * FTOT + n_base + nq * 4);
            int k2 = kk >> 1, p = kk & 1;
            float* b = Bs + (k2 * BS_STRIDE + nq * 4) * 2 + p;
            b[0] = v.x; b[2] = v.y; b[4] = v.z; b[6] = v.w;
        }
        __syncthreads();

        #pragma unroll 4
        for (int k2 = 0; k2 < 32; k2++) {
            union { float4 f[2]; unsigned long long u[4]; } a, b;
            a.f[0] = *(const float4*)(As + (k2 * AS_STRIDE + ty * 4) * 2);
            a.f[1] = *(const float4*)(As + (k2 * AS_STRIDE + ty * 4) * 2 + 4);
            b.f[0] = *(const float4*)(Bs + (k2 * BS_STRIDE + tx * 4) * 2);
            b.f[1] = *(const float4*)(Bs + (k2 * BS_STRIDE + tx * 4) * 2 + 4);
            #pragma unroll
            for (int i = 0; i < 4; i++)
                #pragma unroll
                for (int j = 0; j < 4; j++)
                    asm("fma.rn.f32x2 %0, %1, %2, %0;"
                        : "+l"(acc2[i][j]) : "l"(a.u[i]), "l"(b.u[j]));
        }
        __syncthreads();
    }

    // unpack: acc = lo + hi
    float acc[4][4];
    #pragma unroll
    for (int i = 0; i < 4; i++)
        #pragma unroll
        for (int j = 0; j < 4; j++) {
            unsigned long long v = acc2[i][j];
            acc[i][j] = __uint_as_float((unsigned)v) +
                        __uint_as_float((unsigned)(v >> 32));
        }

    // att vectors for this head / these columns
    float as_v[4], ad_v[4];
    #pragma unroll
    for (int j = 0; j < 4; j++) {
        as_v[j] = __ldg(att_src + n_base + tx * 4 + j);
        ad_v[j] = __ldg(att_dst + n_base + tx * 4 + j);
    }

    #pragma unroll
    for (int i = 0; i < 4; i++) {
        int row = m_base + ty * 4 + i;
        float4 hv = make_float4(acc[i][0], acc[i][1], acc[i][2], acc[i][3]);
        *(float4*)(g_h + (size_t)row * FTOT + n_base + tx * 4) = hv;

        float s1 = acc[i][0] * as_v[0] + acc[i][1] * as_v[1] +
                   acc[i][2] * as_v[2] + acc[i][3] * as_v[3];
        float s2 = acc[i][0] * ad_v[0] + acc[i][1] * ad_v[1] +
                   acc[i][2] * ad_v[2] + acc[i][3] * ad_v[3];
        #pragma unroll
        for (int off = 8; off >= 1; off >>= 1) {
            s1 += __shfl_down_sync(0xffffffffu, s1, off, 16);
            s2 += __shfl_down_sync(0xffffffffu, s2, off, 16);
        }
        if (tx == 0 && row < N) {
            ((float*)&g_asrc[row])[head] = s1;
            ((float*)&g_adst[row])[head] = s2;
        }
    }
}

// ---------------- 3: CSR build ----------------
__global__ void hist_kernel(const unsigned* __restrict__ w, int E, int N) {
    int i = blockIdx.x * blockDim.x + threadIdx.x;
    if (i >= E + N) return;
    int st = g_stride;
    int d = (i < E) ? (int)w[st * E + st * i] : (i - E);
    atomicAdd(&g_cnt[d], 1);
}

__global__ void scan_kernel(int N, int ET, int C) {
    __shared__ int sh[1024];
    int t = threadIdx.x;
    int base = t * C;
    int sum = 0;
    for (int c = 0; c < C; c++) {
        int idx = base + c;
        if (idx < N) sum += g_cnt[idx];
    }
    sh[t] = sum;
    __syncthreads();
    #pragma unroll
    for (int off = 1; off < 1024; off <<= 1) {
        int v = (t >= off) ? sh[t - off] : 0;
        __syncthreads();
        sh[t] += v;
        __syncthreads();
    }
    int run = (t == 0) ? 0 : sh[t - 1];
    for (int c = 0; c < C; c++) {
        int idx = base + c;
        if (idx < N) {
            g_off[idx] = run;
            g_cur[idx] = run;
            run += g_cnt[idx];
        }
    }
    if (t == 1023) g_off[N] = ET;
}

__global__ void scatter_kernel(const unsigned* __restrict__ w, int E, int N) {
    int i = blockIdx.x * blockDim.x + threadIdx.x;
    if (i >= E + N) return;
    int st = g_stride;
    int s, d;
    if (i < E) {
        s = (int)w[st * i];
        d = (int)w[st * E + st * i];
    } else {
        s = d = i - E;
    }
    int pos = atomicAdd(&g_cur[d], 1);
    g_src[pos] = s;
}

// ---------------- 4: softmax denominators (warp per dst node) ----------------
__global__ void alpha_kernel(int N) {
    int gt = blockIdx.x * blockDim.x + threadIdx.x;
    int d = gt >> 5;
    int lane = gt & 31;
    if (d >= N) return;
    int beg = g_off[d], end = g_off[d + 1];
    float4 ad = g_adst[d];
    float sx = 0.f, sy = 0.f, sz = 0.f, sw = 0.f;
    for (int j = beg + lane; j < end; j += 32) {
        int s = g_src[j];
        float4 as = g_asrc[s];
        float4 ex;
        ex.x = __expf(lrelu(as.x + ad.x));
        ex.y = __expf(lrelu(as.y + ad.y));
        ex.z = __expf(lrelu(as.z + ad.z));
        ex.w = __expf(lrelu(as.w + ad.w));
        g_ex[j] = ex;
        sx += ex.x; sy += ex.y; sz += ex.z; sw += ex.w;
    }
    #pragma unroll
    for (int off = 16; off >= 1; off >>= 1) {
        sx += __shfl_xor_sync(0xffffffffu, sx, off);
        sy += __shfl_xor_sync(0xffffffffu, sy, off);
        sz += __shfl_xor_sync(0xffffffffu, sz, off);
        sw += __shfl_xor_sync(0xffffffffu, sw, off);
    }
    if (lane == 0)
        g_inv[d] = make_float4(1.0f / (sx + 1e-16f), 1.0f / (sy + 1e-16f),
                               1.0f / (sz + 1e-16f), 1.0f / (sw + 1e-16f));
}

// ---------------- 5: aggregate + bias + mix-ELU (warp per dst node) --------
__device__ __forceinline__ float mixelu(float z) {
    float e = z > 0.0f ? z : expm1f(z);
    return 0.5f * z + 0.5f * e;
}

__global__ void agg_kernel(float* __restrict__ out,
                           const float* __restrict__ bias, int N) {
    int gt = blockIdx.x * blockDim.x + threadIdx.x;
    int d = gt >> 5;
    int lane = gt & 31;
    if (d >= N) return;
    int beg = g_off[d], end = g_off[d + 1];
    float4 inv = g_inv[d];
    bool hi = (lane & 16) != 0;
    float inv0 = hi ? inv.y : inv.x;
    float inv1 = hi ? inv.w : inv.z;

    float4 r0 = make_float4(0.f, 0.f, 0.f, 0.f);
    float4 r1 = make_float4(0.f, 0.f, 0.f, 0.f);

    #pragma unroll 2
    for (int j = beg; j < end; j++) {
        int s = __ldg(&g_src[j]);
        float4 ex = __ldg(&g_ex[j]);
        float a0 = (hi ? ex.y : ex.x) * inv0;
        float a1 = (hi ? ex.w : ex.z) * inv1;
        const float4* hrow = (const float4*)(g_h + (size_t)s * FTOT);
        float4 h0 = __ldg(hrow + lane);
        float4 h1 = __ldg(hrow + lane + 32);
        r0.x = fmaf(a0, h0.x, r0.x); r0.y = fmaf(a0, h0.y, r0.y);
        r0.z = fmaf(a0, h0.z, r0.z); r0.w = fmaf(a0, h0.w, r0.w);
        r1.x = fmaf(a1, h1.x, r1.x); r1.y = fmaf(a1, h1.y, r1.y);
        r1.z = fmaf(a1, h1.z, r1.z); r1.w = fmaf(a1, h1.w, r1.w);
    }

    float4 b0 = __ldg((const float4*)bias + lane);
    float4 b1 = __ldg((const float4*)bias + lane + 32);
    float4 o0, o1;
    o0.x = mixelu(r0.x + b0.x); o0.y = mixelu(r0.y + b0.y);
    o0.z = mixelu(r0.z + b0.z); o0.w = mixelu(r0.w + b0.w);
    o1.x = mixelu(r1.x + b1.x); o1.y = mixelu(r1.y + b1.y);
    o1.z = mixelu(r1.z + b1.z); o1.w = mixelu(r1.w + b1.w);

    float4* orow = (float4*)(out + (size_t)d * FTOT);
    orow[lane] = o0;
    orow[lane + 32] = o1;
}

// ---------------- launch ----------------
extern "C" void kernel_launch(void* const* d_in, const int* in_sizes, int n_in,
                              void* d_out, int out_size) {
    const float*    x       = (const float*)d_in[0];
    const unsigned* edge    = (const unsigned*)d_in[1];
    const float*    W       = (const float*)d_in[2];
    const float*    att_src = (const float*)d_in[3];
    const float*    att_dst = (const float*)d_in[4];
    const float*    bias    = (const float*)d_in[5];
    float*          out     = (float*)d_out;

    const int N = in_sizes[0] / IN_DIM;        // 50000
    const int E = in_sizes[1] / 2;             // 800000
    const int ET = E + N;

    detect_kernel<<<1, 32>>>(edge);
    zero_cnt_kernel<<<(N + 255) / 256, 256>>>(N);

    {
        dim3 grid((N + 63) / 64, HEADS);
        gemm_kernel<<<grid, 256>>>(x, W, att_src, att_dst, N);
    }

    hist_kernel<<<(ET + 255) / 256, 256>>>(edge, E, N);
    scan_kernel<<<1, 1024>>>(N, ET, (N + 1023) / 1024);
    scatter_kernel<<<(ET + 255) / 256, 256>>>(edge, E, N);

    alpha_kernel<<<((long)N * 32 + 255) / 256, 256>>>(N);
    agg_kernel<<<((long)N * 32 + 255) / 256, 256>>>(out, bias, N);
}

// round 3
// speedup vs baseline: 1.3341x; 1.3021x over previous
#include <cuda_runtime.h>
#include <cstdint>

#define MAXN 50048          // 782 * 64
#define MAXE 860032         // >= E + N
#define IN_DIM 128
#define HEADS 4
#define OUT_DIM 64
#define FTOT 256

// ---------------- scratch ----------------
__device__ float  g_h[(size_t)MAXN * FTOT];     // 51.25 MB
__device__ float4 g_asrc[MAXN];
__device__ float4 g_adst[MAXN];
__device__ int    g_src[MAXE];                  // CSR src, sorted by dst
__device__ int    g_cnt[MAXN];
__device__ int    g_off[MAXN + 1];
__device__ int    g_cur[MAXN];
__device__ int    g_stride;                     // 1 = int32 edges, 2 = int64

__device__ __forceinline__ float lrelu(float e) {
    return e > 0.0f ? e : 0.2f * e;
}

// ---------------- 0: edge dtype detection ----------------
__global__ void detect_kernel(const unsigned* __restrict__ w) {
    if (threadIdx.x == 0) {
        int is64 = 1;
        #pragma unroll 1
        for (int j = 1; j < 64; j += 2)
            if (w[j] != 0u) { is64 = 0; break; }
        g_stride = is64 ? 2 : 1;
    }
}

// ---------------- 1: zero degree counters ----------------
__global__ void zero_cnt_kernel(int N) {
    int i = blockIdx.x * blockDim.x + threadIdx.x;
    if (i < N) g_cnt[i] = 0;
}

// ---------------- 2: CSR build ----------------
__global__ void hist_kernel(const unsigned* __restrict__ w, int E, int N) {
    int i = blockIdx.x * blockDim.x + threadIdx.x;
    if (i >= E + N) return;
    int st = g_stride;
    int d = (i < E) ? (int)w[st * E + st * i] : (i - E);
    atomicAdd(&g_cnt[d], 1);
}

__global__ void scan_kernel(int N, int ET, int C) {
    __shared__ int sh[1024];
    int t = threadIdx.x;
    int base = t * C;
    int sum = 0;
    #pragma unroll 4
    for (int c = 0; c < C; c++) {
        int idx = base + c;
        if (idx < N) sum += g_cnt[idx];
    }
    sh[t] = sum;
    __syncthreads();
    #pragma unroll
    for (int off = 1; off < 1024; off <<= 1) {
        int v = (t >= off) ? sh[t - off] : 0;
        __syncthreads();
        sh[t] += v;
        __syncthreads();
    }
    int run = (t == 0) ? 0 : sh[t - 1];
    for (int c = 0; c < C; c++) {
        int idx = base + c;
        if (idx < N) {
            g_off[idx] = run;
            g_cur[idx] = run;
            run += g_cnt[idx];
        }
    }
    if (t == 1023) g_off[N] = ET;
}

__global__ void scatter_kernel(const unsigned* __restrict__ w, int E, int N) {
    int i = blockIdx.x * blockDim.x + threadIdx.x;
    if (i >= E + N) return;
    int st = g_stride;
    int s, d;
    if (i < E) {
        s = (int)w[st * i];
        d = (int)w[st * E + st * i];
    } else {
        s = d = i - E;
    }
    int pos = atomicAdd(&g_cur[d], 1);
    g_src[pos] = s;
}

// ---------------- 3: GEMM h = x @ W (packed f32x2 FMA) ----------------
// 64x64 tile / 256 threads; K as 64 k-pairs (2 chunks of 32).
// A tile: row-pair interleaved (pairs of (x[r][2k2],x[r][2k2+1])), broadcast reads.
// B tile: split into BsA/BsB so each inner-loop LDS.128 is 16B/thread with
// lane l hitting banks 4l..4l+3 -> conflict-free.
#define AS_STRIDE 66   // float2 units per k2 row

__global__ void __launch_bounds__(256)
gemm_kernel(const float* __restrict__ x,
            const float* __restrict__ W,
            const float* __restrict__ att_src,
            const float* __restrict__ att_dst, int N) {
    __shared__ float As[32 * AS_STRIDE * 2];    // 4224 floats
    __shared__ float BsA[32 * 16 * 4];          // 2048 floats
    __shared__ float BsB[32 * 16 * 4];          // 2048 floats
    const int tid = threadIdx.x;
    const int m_base = blockIdx.x * 64;
    const int head = blockIdx.y;
    const int n_base = head * OUT_DIM;
    const int tx = tid & 15;
    const int ty = tid >> 4;

    unsigned long long acc2[4][4];
    #pragma unroll
    for (int i = 0; i < 4; i++)
        #pragma unroll
        for (int j = 0; j < 4; j++) acc2[i][j] = 0ULL;

    #pragma unroll 1
    for (int kc = 0; kc < 2; kc++) {
        // As fill: As[(k2*AS + r)*2 + {0,1}] = (x[row][2k2], x[row][2k2+1])
        #pragma unroll
        for (int t = 0; t < 8; t++) {
            int idx = tid + t * 256;            // 0..2047
            int r = idx >> 5;
            int k2 = idx & 31;
            int row = m_base + r;
            if (row >= N) row = N - 1;
            float2 v = *(const float2*)(x + row * IN_DIM + kc * 64 + k2 * 2);
            *(float2*)(As + (k2 * AS_STRIDE + r) * 2) = v;
        }
        // Bs fill: cols (4nq,4nq+1) pairs -> BsA, cols (4nq+2,4nq+3) -> BsB
        #pragma unroll
        for (int t = 0; t < 4; t++) {
            int q = tid + t * 256;              // 0..1023 float4s
            int kk = q >> 4;                    // K index within chunk
            int nq = q & 15;
            float4 v = *(const float4*)(W + (kc * 64 + kk) * FTOT + n_base + nq * 4);
            int k2 = kk >> 1, p = kk & 1;
            int base = (k2 * 16 + nq) * 4;
            BsA[base + 0 + p] = v.x;
            BsA[base + 2 + p] = v.y;
            BsB[base + 0 + p] = v.z;
            BsB[base + 2 + p] = v.w;
        }
        __syncthreads();

        #pragma unroll 4
        for (int k2 = 0; k2 < 32; k2++) {
            union { float4 f[2]; unsigned long long u[4]; } a, b;
            a.f[0] = *(const float4*)(As + (k2 * AS_STRIDE + ty * 4) * 2);
            a.f[1] = *(const float4*)(As + (k2 * AS_STRIDE + ty * 4) * 2 + 4);
            b.f[0] = *(const float4*)(BsA + (k2 * 16 + tx) * 4);
            b.f[1] = *(const float4*)(BsB + (k2 * 16 + tx) * 4);
            #pragma unroll
            for (int i = 0; i < 4; i++)
                #pragma unroll
                for (int j = 0; j < 4; j++)
                    asm("fma.rn.f32x2 %0, %1, %2, %0;"
                        : "+l"(acc2[i][j]) : "l"(a.u[i]), "l"(b.u[j]));
        }
        __syncthreads();
    }

    float acc[4][4];
    #pragma unroll
    for (int i = 0; i < 4; i++)
        #pragma unroll
        for (int j = 0; j < 4; j++) {
            unsigned long long v = acc2[i][j];
            acc[i][j] = __uint_as_float((unsigned)v) +
                        __uint_as_float((unsigned)(v >> 32));
        }

    float as_v[4], ad_v[4];
    #pragma unroll
    for (int j = 0; j < 4; j++) {
        as_v[j] = __ldg(att_src + n_base + tx * 4 + j);
        ad_v[j] = __ldg(att_dst + n_base + tx * 4 + j);
    }

    #pragma unroll
    for (int i = 0; i < 4; i++) {
        int row = m_base + ty * 4 + i;
        float4 hv = make_float4(acc[i][0], acc[i][1], acc[i][2], acc[i][3]);
        *(float4*)(g_h + (size_t)row * FTOT + n_base + tx * 4) = hv;

        float s1 = acc[i][0] * as_v[0] + acc[i][1] * as_v[1] +
                   acc[i][2] * as_v[2] + acc[i][3] * as_v[3];
        float s2 = acc[i][0] * ad_v[0] + acc[i][1] * ad_v[1] +
                   acc[i][2] * ad_v[2] + acc[i][3] * ad_v[3];
        #pragma unroll
        for (int off = 8; off >= 1; off >>= 1) {
            s1 += __shfl_down_sync(0xffffffffu, s1, off, 16);
            s2 += __shfl_down_sync(0xffffffffu, s2, off, 16);
        }
        if (tx == 0 && row < N) {
            ((float*)&g_asrc[row])[head] = s1;
            ((float*)&g_adst[row])[head] = s2;
        }
    }
}

// ---------------- 4: fused softmax + aggregate + bias + mix-ELU ------------
// One warp per dst node. out[d] = (sum_e ex_e * h[src_e]) / (sum_e ex_e + eps),
// normalization applied after accumulation, so a single pass suffices.
__device__ __forceinline__ float mixelu(float z) {
    float e = z > 0.0f ? z : expm1f(z);
    return 0.5f * z + 0.5f * e;
}

__global__ void __launch_bounds__(256)
agg_kernel(float* __restrict__ out, const float* __restrict__ bias, int N) {
    int gt = blockIdx.x * blockDim.x + threadIdx.x;
    int d = gt >> 5;
    int lane = gt & 31;
    if (d >= N) return;
    int beg = g_off[d], end = g_off[d + 1];
    bool hi = (lane & 16) != 0;

    float4 ad = g_adst[d];                      // broadcast
    float ad0 = hi ? ad.y : ad.x;               // head for r0 chunk
    float ad1 = hi ? ad.w : ad.z;               // head for r1 chunk

    float4 r0 = make_float4(0.f, 0.f, 0.f, 0.f);
    float4 r1 = make_float4(0.f, 0.f, 0.f, 0.f);
    float s0 = 0.f, s1 = 0.f;

    #pragma unroll 2
    for (int j = beg; j < end; j++) {
        int s = __ldg(&g_src[j]);
        float4 as = __ldg(&g_asrc[s]);          // broadcast gather
        float e0 = __expf(lrelu((hi ? as.y : as.x) + ad0));
        float e1 = __expf(lrelu((hi ? as.w : as.z) + ad1));
        s0 += e0; s1 += e1;
        const float4* hrow = (const float4*)(g_h + (size_t)s * FTOT);
        float4 h0 = __ldg(hrow + lane);
        float4 h1 = __ldg(hrow + lane + 32);
        r0.x = fmaf(e0, h0.x, r0.x); r0.y = fmaf(e0, h0.y, r0.y);
        r0.z = fmaf(e0, h0.z, r0.z); r0.w = fmaf(e0, h0.w, r0.w);
        r1.x = fmaf(e1, h1.x, r1.x); r1.y = fmaf(e1, h1.y, r1.y);
        r1.z = fmaf(e1, h1.z, r1.z); r1.w = fmaf(e1, h1.w, r1.w);
    }

    float inv0 = 1.0f / (s0 + 1e-16f);
    float inv1 = 1.0f / (s1 + 1e-16f);

    float4 b0 = __ldg((const float4*)bias + lane);
    float4 b1 = __ldg((const float4*)bias + lane + 32);
    float4 o0, o1;
    o0.x = mixelu(r0.x * inv0 + b0.x); o0.y = mixelu(r0.y * inv0 + b0.y);
    o0.z = mixelu(r0.z * inv0 + b0.z); o0.w = mixelu(r0.w * inv0 + b0.w);
    o1.x = mixelu(r1.x * inv1 + b1.x); o1.y = mixelu(r1.y * inv1 + b1.y);
    o1.z = mixelu(r1.z * inv1 + b1.z); o1.w = mixelu(r1.w * inv1 + b1.w);

    float4* orow = (float4*)(out + (size_t)d * FTOT);
    orow[lane] = o0;
    orow[lane + 32] = o1;
}

// ---------------- launch ----------------
extern "C" void kernel_launch(void* const* d_in, const int* in_sizes, int n_in,
                              void* d_out, int out_size) {
    const float*    x       = (const float*)d_in[0];
    const unsigned* edge    = (const unsigned*)d_in[1];
    const float*    W       = (const float*)d_in[2];
    const float*    att_src = (const float*)d_in[3];
    const float*    att_dst = (const float*)d_in[4];
    const float*    bias    = (const float*)d_in[5];
    float*          out     = (float*)d_out;

    const int N = in_sizes[0] / IN_DIM;        // 50000
    const int E = in_sizes[1] / 2;             // 800000
    const int ET = E + N;

    detect_kernel<<<1, 32>>>(edge);                                   // 1
    zero_cnt_kernel<<<(N + 255) / 256, 256>>>(N);                     // 2
    hist_kernel<<<(ET + 255) / 256, 256>>>(edge, E, N);               // 3
    {
        dim3 grid((N + 63) / 64, HEADS);
        gemm_kernel<<<grid, 256>>>(x, W, att_src, att_dst, N);        // 4 (profiled slot)
    }
    scan_kernel<<<1, 1024>>>(N, ET, (N + 1023) / 1024);               // 5
    scatter_kernel<<<(ET + 255) / 256, 256>>>(edge, E, N);            // 6
    agg_kernel<<<((long)N * 32 + 255) / 256, 256>>>(out, bias, N);    // 7
}

// round 4
// speedup vs baseline: 1.8460x; 1.3837x over previous
#include <cuda_runtime.h>
#include <cstdint>

#define MAXN 50048          // 391 * 128
#define MAXE 860032         // >= E + N
#define IN_DIM 128
#define HEADS 4
#define OUT_DIM 64
#define FTOT 256

// ---------------- scratch ----------------
__device__ float  g_h[(size_t)MAXN * FTOT];     // 51.25 MB
__device__ float4 g_asrc[MAXN];
__device__ float4 g_adst[MAXN];
__device__ int    g_src[MAXE];                  // CSR src, sorted by dst
__device__ int    g_cnt[MAXN];
__device__ int    g_off[MAXN + 1];
__device__ int    g_cur[MAXN];
__device__ int    g_bsum[256];
__device__ int    g_boff[256];

__device__ __forceinline__ float lrelu(float e) {
    return e > 0.0f ? e : 0.2f * e;
}

// detect int64 vs int32 edge dtype from the first 64 words (per block, cached)
__device__ __forceinline__ int edge_stride(const unsigned* w) {
    int is64 = 1;
    #pragma unroll 1
    for (int j = 1; j < 64; j += 2)
        if (w[j] != 0u) { is64 = 0; break; }
    return is64 ? 2 : 1;
}

// ---------------- 1: zero degree counters ----------------
__global__ void zero_cnt_kernel(int N) {
    int i = blockIdx.x * blockDim.x + threadIdx.x;
    if (i < N) g_cnt[i] = 0;
}

// ---------------- 2: histogram ----------------
__global__ void hist_kernel(const unsigned* __restrict__ w, int E, int N) {
    __shared__ int s_st;
    if (threadIdx.x == 0) s_st = edge_stride(w);
    __syncthreads();
    int st = s_st;
    int i = blockIdx.x * blockDim.x + threadIdx.x;
    if (i >= E + N) return;
    int d = (i < E) ? (int)w[st * E + st * i] : (i - E);
    atomicAdd(&g_cnt[d], 1);
}

// ---------------- 3: three-phase exclusive scan of g_cnt ----------------
__global__ void scan_a_kernel(int N) {
    __shared__ int sh[256];
    int idx = blockIdx.x * 256 + threadIdx.x;
    int v = (idx < N) ? g_cnt[idx] : 0;
    sh[threadIdx.x] = v;
    __syncthreads();
    #pragma unroll
    for (int off = 128; off >= 1; off >>= 1) {
        if (threadIdx.x < off) sh[threadIdx.x] += sh[threadIdx.x + off];
        __syncthreads();
    }
    if (threadIdx.x == 0) g_bsum[blockIdx.x] = sh[0];
}

__global__ void scan_b_kernel(int GB) {
    __shared__ int sh[256];
    int t = threadIdx.x;
    int v = (t < GB) ? g_bsum[t] : 0;
    sh[t] = v;
    __syncthreads();
    #pragma unroll
    for (int off = 1; off < 256; off <<= 1) {
        int u = (t >= off) ? sh[t - off] : 0;
        __syncthreads();
        sh[t] += u;
        __syncthreads();
    }
    g_boff[t] = sh[t] - v;      // exclusive
}

__global__ void scan_c_kernel(int N, int ET) {
    __shared__ int sh[256];
    int t = threadIdx.x;
    int idx = blockIdx.x * 256 + t;
    int c = (idx < N) ? g_cnt[idx] : 0;
    sh[t] = c;
    __syncthreads();
    #pragma unroll
    for (int off = 1; off < 256; off <<= 1) {
        int u = (t >= off) ? sh[t - off] : 0;
        __syncthreads();
        sh[t] += u;
        __syncthreads();
    }
    int ex = g_boff[blockIdx.x] + sh[t] - c;
    if (idx < N) {
        g_off[idx] = ex;
        g_cur[idx] = ex;
        if (idx == N - 1) g_off[N] = ET;
    }
}

// ---------------- 4: GEMM h = x @ W (packed f32x2, 128x64 block tile) ------
// 256 threads, thread tile 8 rows x 4 cols; K in 4 chunks of 32 (16 k-pairs).
// A fragments are warp-broadcast (address depends on ty only); B split BsA/BsB
// keeps the 16-thread-span loads at 2 LDS.128 per iteration.
#define AS 130   // float2 units per k2 row (128 rows + 2 pad; keeps 16B align)

__global__ void __launch_bounds__(256, 2)
gemm_kernel(const float* __restrict__ x,
            const float* __restrict__ W,
            const float* __restrict__ att_src,
            const float* __restrict__ att_dst, int N) {
    __shared__ float As_[16 * AS * 2];          // 16.6 KB
    __shared__ float BsA[16 * 16 * 4];          // 4 KB
    __shared__ float BsB[16 * 16 * 4];          // 4 KB
    const int tid = threadIdx.x;
    const int m_base = blockIdx.x * 128;
    const int head = blockIdx.y;
    const int n_base = head * OUT_DIM;
    const int tx = tid & 15;
    const int ty = tid >> 4;

    unsigned long long acc2[8][4];
    #pragma unroll
    for (int i = 0; i < 8; i++)
        #pragma unroll
        for (int j = 0; j < 4; j++) acc2[i][j] = 0ULL;

    #pragma unroll 1
    for (int kc = 0; kc < 4; kc++) {
        // A fill: As_[(k2*AS + r)*2 + {0,1}] = (x[row][2k2], x[row][2k2+1])
        #pragma unroll
        for (int t = 0; t < 8; t++) {
            int idx = tid + t * 256;            // 0..2047
            int r = idx >> 4;                   // 0..127
            int k2 = idx & 15;                  // 0..15
            int row = m_base + r;
            if (row >= N) row = N - 1;
            float2 v = *(const float2*)(x + row * IN_DIM + kc * 32 + k2 * 2);
            *(float2*)(As_ + (k2 * AS + r) * 2) = v;
        }
        // B fill: cols (4nq,4nq+1) -> BsA, (4nq+2,4nq+3) -> BsB
        #pragma unroll
        for (int t = 0; t < 2; t++) {
            int q = tid + t * 256;              // 0..511 float4s
            int kk = q >> 4;                    // 0..31
            int nq = q & 15;
            float4 v = *(const float4*)(W + (kc * 32 + kk) * FTOT + n_base + nq * 4);
            int k2 = kk >> 1, p = kk & 1;
            int base = (k2 * 16 + nq) * 4;
            BsA[base + 0 + p] = v.x;
            BsA[base + 2 + p] = v.y;
            BsB[base + 0 + p] = v.z;
            BsB[base + 2 + p] = v.w;
        }
        __syncthreads();

        #pragma unroll 4
        for (int k2 = 0; k2 < 16; k2++) {
            union { float4 f[4]; unsigned long long u[8]; } a;
            union { float4 f[2]; unsigned long long u[4]; } b;
            const float* ap = As_ + (k2 * AS + ty * 8) * 2;
            a.f[0] = *(const float4*)(ap + 0);
            a.f[1] = *(const float4*)(ap + 4);
            a.f[2] = *(const float4*)(ap + 8);
            a.f[3] = *(const float4*)(ap + 12);
            b.f[0] = *(const float4*)(BsA + (k2 * 16 + tx) * 4);
            b.f[1] = *(const float4*)(BsB + (k2 * 16 + tx) * 4);
            #pragma unroll
            for (int i = 0; i < 8; i++)
                #pragma unroll
                for (int j = 0; j < 4; j++)
                    asm("fma.rn.f32x2 %0, %1, %2, %0;"
                        : "+l"(acc2[i][j]) : "l"(a.u[i]), "l"(b.u[j]));
        }
        __syncthreads();
    }

    float as_v[4], ad_v[4];
    #pragma unroll
    for (int j = 0; j < 4; j++) {
        as_v[j] = __ldg(att_src + n_base + tx * 4 + j);
        ad_v[j] = __ldg(att_dst + n_base + tx * 4 + j);
    }

    #pragma unroll
    for (int i = 0; i < 8; i++) {
        float acc[4];
        #pragma unroll
        for (int j = 0; j < 4; j++) {
            unsigned long long v = acc2[i][j];
            acc[j] = __uint_as_float((unsigned)v) +
                     __uint_as_float((unsigned)(v >> 32));
        }
        int row = m_base + ty * 8 + i;
        float4 hv = make_float4(acc[0], acc[1], acc[2], acc[3]);
        *(float4*)(g_h + (size_t)row * FTOT + n_base + tx * 4) = hv;

        float s1 = acc[0] * as_v[0] + acc[1] * as_v[1] +
                   acc[2] * as_v[2] + acc[3] * as_v[3];
        float s2 = acc[0] * ad_v[0] + acc[1] * ad_v[1] +
                   acc[2] * ad_v[2] + acc[3] * ad_v[3];
        #pragma unroll
        for (int off = 8; off >= 1; off >>= 1) {
            s1 += __shfl_down_sync(0xffffffffu, s1, off, 16);
            s2 += __shfl_down_sync(0xffffffffu, s2, off, 16);
        }
        if (tx == 0 && row < N) {
            ((float*)&g_asrc[row])[head] = s1;
            ((float*)&g_adst[row])[head] = s2;
        }
    }
}

// ---------------- 5: scatter (CSR fill) ----------------
__global__ void scatter_kernel(const unsigned* __restrict__ w, int E, int N) {
    __shared__ int s_st;
    if (threadIdx.x == 0) s_st = edge_stride(w);
    __syncthreads();
    int st = s_st;
    int i = blockIdx.x * blockDim.x + threadIdx.x;
    if (i >= E + N) return;
    int s, d;
    if (i < E) {
        s = (int)w[st * i];
        d = (int)w[st * E + st * i];
    } else {
        s = d = i - E;
    }
    int pos = atomicAdd(&g_cur[d], 1);
    g_src[pos] = s;
}

// ---------------- 6: fused softmax + aggregate + bias + mix-ELU ------------
__device__ __forceinline__ float mixelu(float z) {
    float e = z > 0.0f ? z : expm1f(z);
    return 0.5f * z + 0.5f * e;
}

__global__ void __launch_bounds__(256)
agg_kernel(float* __restrict__ out, const float* __restrict__ bias, int N) {
    int gt = blockIdx.x * blockDim.x + threadIdx.x;
    int d = gt >> 5;
    int lane = gt & 31;
    if (d >= N) return;
    int beg = g_off[d], end = g_off[d + 1];
    bool hi = (lane & 16) != 0;

    float4 ad = g_adst[d];
    float ad0 = hi ? ad.y : ad.x;
    float ad1 = hi ? ad.w : ad.z;

    float4 r0 = make_float4(0.f, 0.f, 0.f, 0.f);
    float4 r1 = make_float4(0.f, 0.f, 0.f, 0.f);
    float s0 = 0.f, s1 = 0.f;

    #pragma unroll 2
    for (int j = beg; j < end; j++) {
        int s = __ldg(&g_src[j]);
        float4 as = __ldg(&g_asrc[s]);
        float e0 = __expf(lrelu((hi ? as.y : as.x) + ad0));
        float e1 = __expf(lrelu((hi ? as.w : as.z) + ad1));
        s0 += e0; s1 += e1;
        const float4* hrow = (const float4*)(g_h + (size_t)s * FTOT);
        float4 h0 = __ldg(hrow + lane);
        float4 h1 = __ldg(hrow + lane + 32);
        r0.x = fmaf(e0, h0.x, r0.x); r0.y = fmaf(e0, h0.y, r0.y);
        r0.z = fmaf(e0, h0.z, r0.z); r0.w = fmaf(e0, h0.w, r0.w);
        r1.x = fmaf(e1, h1.x, r1.x); r1.y = fmaf(e1, h1.y, r1.y);
        r1.z = fmaf(e1, h1.z, r1.z); r1.w = fmaf(e1, h1.w, r1.w);
    }

    float inv0 = 1.0f / (s0 + 1e-16f);
    float inv1 = 1.0f / (s1 + 1e-16f);

    float4 b0 = __ldg((const float4*)bias + lane);
    float4 b1 = __ldg((const float4*)bias + lane + 32);
    float4 o0, o1;
    o0.x = mixelu(r0.x * inv0 + b0.x); o0.y = mixelu(r0.y * inv0 + b0.y);
    o0.z = mixelu(r0.z * inv0 + b0.z); o0.w = mixelu(r0.w * inv0 + b0.w);
    o1.x = mixelu(r1.x * inv1 + b1.x); o1.y = mixelu(r1.y * inv1 + b1.y);
    o1.z = mixelu(r1.z * inv1 + b1.z); o1.w = mixelu(r1.w * inv1 + b1.w);

    float4* orow = (float4*)(out + (size_t)d * FTOT);
    orow[lane] = o0;
    orow[lane + 32] = o1;
}

// ---------------- launch ----------------
extern "C" void kernel_launch(void* const* d_in, const int* in_sizes, int n_in,
                              void* d_out, int out_size) {
    const float*    x       = (const float*)d_in[0];
    const unsigned* edge    = (const unsigned*)d_in[1];
    const float*    W       = (const float*)d_in[2];
    const float*    att_src = (const float*)d_in[3];
    const float*    att_dst = (const float*)d_in[4];
    const float*    bias    = (const float*)d_in[5];
    float*          out     = (float*)d_out;

    const int N = in_sizes[0] / IN_DIM;        // 50000
    const int E = in_sizes[1] / 2;             // 800000
    const int ET = E + N;
    const int GB = (N + 255) / 256;            // 196 scan blocks

    zero_cnt_kernel<<<(N + 255) / 256, 256>>>(N);                     // 1
    hist_kernel<<<(ET + 255) / 256, 256>>>(edge, E, N);               // 2
    scan_a_kernel<<<GB, 256>>>(N);                                    // 3
    {
        dim3 grid((N + 127) / 128, HEADS);
        gemm_kernel<<<grid, 256>>>(x, W, att_src, att_dst, N);        // 4 (profiled)
    }
    scan_b_kernel<<<1, 256>>>(GB);                                    // 5
    scan_c_kernel<<<GB, 256>>>(N, ET);                                // 6
    scatter_kernel<<<(ET + 255) / 256, 256>>>(edge, E, N);            // 7
    agg_kernel<<<((long)N * 32 + 255) / 256, 256>>>(out, bias, N);    // 8
}

// round 6
// speedup vs baseline: 2.1158x; 1.1461x over previous
#include <cuda_runtime.h>
#include <cuda_bf16.h>
#include <cuda_fp16.h>
#include <cstdint>

#define MAXN 50048
#define MAXE 860032
#define IN_DIM 128
#define HEADS 4
#define OUT_DIM 64
#define FTOT 256

// ---------------- scratch ----------------
__device__ unsigned g_hh[(size_t)MAXN * 128];   // h as half2 pairs: 25.6 MB
__device__ float4 g_asrc[MAXN];
__device__ float4 g_adst[MAXN];
__device__ int    g_src[MAXE];
__device__ int    g_cnt[MAXN];
__device__ int    g_off[MAXN + 1];
__device__ int    g_cur[MAXN];
__device__ int    g_bsum[256];
__device__ int    g_boff[256];
__device__ __nv_bfloat16 g_wthi[FTOT * IN_DIM]; // W^T hi: [n][k]
__device__ __nv_bfloat16 g_wtlo[FTOT * IN_DIM]; // W^T lo

__device__ __forceinline__ float lrelu(float e) {
    return e > 0.0f ? e : 0.2f * e;
}

__device__ __forceinline__ int edge_stride(const unsigned* w) {
    int is64 = 1;
    #pragma unroll 1
    for (int j = 1; j < 64; j += 2)
        if (w[j] != 0u) { is64 = 0; break; }
    return is64 ? 2 : 1;
}

// ---------------- 1: zero degree counters ----------------
__global__ void zero_cnt_kernel(int N) {
    int i = blockIdx.x * blockDim.x + threadIdx.x;
    if (i < N) g_cnt[i] = 0;
}

// ---------------- 2: histogram ----------------
__global__ void hist_kernel(const unsigned* __restrict__ w, int E, int N) {
    __shared__ int s_st;
    if (threadIdx.x == 0) s_st = edge_stride(w);
    __syncthreads();
    int st = s_st;
    int i = blockIdx.x * blockDim.x + threadIdx.x;
    if (i >= E + N) return;
    int d = (i < E) ? (int)w[st * E + st * i] : (i - E);
    atomicAdd(&g_cnt[d], 1);
}

// ---------------- 3: W transpose + bf16 hi/lo split ----------------
__global__ void wt_kernel(const float* __restrict__ W) {
    int i = blockIdx.x * 256 + threadIdx.x;     // 0..32767
    int k = i & 127, n = i >> 7;
    float v = __ldg(W + (size_t)k * FTOT + n);
    __nv_bfloat16 h = __float2bfloat16_rn(v);
    g_wthi[i] = h;
    g_wtlo[i] = __float2bfloat16_rn(v - __bfloat162float(h));
}

// ---------------- 4: GEMM on HMMA (split-bf16, 3 passes) ----------------
// Block: 256 thr (8 warps = 4m x 2n), tile 128 rows x 64 cols (one head).
// K staged in 2 chunks of 64. A/B smem pitch 72 halves (conflict-free frags).
// D = A_hi@B_hi + A_hi@B_lo + A_lo@B_hi, fp32 accum.
#define PA 72
#define SM_A_HI 0
#define SM_A_LO 18432
#define SM_B_HI 36864
#define SM_B_LO 46080
#define SM_ATT  55296
#define SMEM_BYTES 55808

__global__ void __launch_bounds__(256)
gemm_kernel(const float* __restrict__ x,
            const float* __restrict__ att_src,
            const float* __restrict__ att_dst, int N) {
    extern __shared__ __align__(16) char sm[];
    __nv_bfloat16* Ahi = (__nv_bfloat16*)(sm + SM_A_HI);
    __nv_bfloat16* Alo = (__nv_bfloat16*)(sm + SM_A_LO);
    __nv_bfloat16* Bhi = (__nv_bfloat16*)(sm + SM_B_HI);
    __nv_bfloat16* Blo = (__nv_bfloat16*)(sm + SM_B_LO);
    float* attm = (float*)(sm + SM_ATT);

    const int tid = threadIdx.x;
    const int lane = tid & 31, wid = tid >> 5;
    const int mw = wid & 3, nw = wid >> 2;
    const int m_base = blockIdx.x * 128, head = blockIdx.y;
    const int n_base = head * OUT_DIM;

    if (tid < 64) {
        attm[tid] = __ldg(att_src + n_base + tid);
        attm[64 + tid] = __ldg(att_dst + n_base + tid);
    }

    float acc[2][4][4];
    #pragma unroll
    for (int mt = 0; mt < 2; mt++)
        #pragma unroll
        for (int nt = 0; nt < 4; nt++)
            #pragma unroll
            for (int c = 0; c < 4; c++) acc[mt][nt][c] = 0.0f;

    const int arow = tid >> 1, aseg = tid & 1;
    int grow = m_base + arow;
    if (grow >= N) grow = N - 1;

    const int aoff = (mw * 32 + (lane >> 2)) * PA + (lane & 3) * 2;
    const int boff = (nw * 32 + (lane >> 2)) * PA + (lane & 3) * 2;

    #pragma unroll 1
    for (int chunk = 0; chunk < 2; chunk++) {
        if (chunk) __syncthreads();
        // ---- A fill: 128 rows x 64 k, bf16 hi/lo ----
        {
            const float4* xs = (const float4*)(x + (size_t)grow * IN_DIM +
                                               chunk * 64 + aseg * 32);
            __nv_bfloat16* ah = Ahi + arow * PA + aseg * 32;
            __nv_bfloat16* al = Alo + arow * PA + aseg * 32;
            #pragma unroll
            for (int i = 0; i < 8; i++) {
                float4 v = __ldg(xs + i);
                __nv_bfloat162 h01, h23, l01, l23;
                h01.x = __float2bfloat16_rn(v.x);
                h01.y = __float2bfloat16_rn(v.y);
                h23.x = __float2bfloat16_rn(v.z);
                h23.y = __float2bfloat16_rn(v.w);
                l01.x = __float2bfloat16_rn(v.x - __bfloat162float(h01.x));
                l01.y = __float2bfloat16_rn(v.y - __bfloat162float(h01.y));
                l23.x = __float2bfloat16_rn(v.z - __bfloat162float(h23.x));
                l23.y = __float2bfloat16_rn(v.w - __bfloat162float(h23.y));
                uint2 uh, ul;
                uh.x = *reinterpret_cast<unsigned*>(&h01);
                uh.y = *reinterpret_cast<unsigned*>(&h23);
                ul.x = *reinterpret_cast<unsigned*>(&l01);
                ul.y = *reinterpret_cast<unsigned*>(&l23);
                *(uint2*)(ah + i * 4) = uh;
                *(uint2*)(al + i * 4) = ul;
            }
        }
        // ---- B fill: 64 n-rows x 64 k from pre-split W^T ----
        {
            int bn = tid >> 2, q = tid & 3;
            const uint2* shh = (const uint2*)(g_wthi + (size_t)(n_base + bn) * IN_DIM + chunk * 64);
            const uint2* shl = (const uint2*)(g_wtlo + (size_t)(n_base + bn) * IN_DIM + chunk * 64);
            uint2* dhh = (uint2*)(Bhi + bn * PA);
            uint2* dhl = (uint2*)(Blo + bn * PA);
            #pragma unroll
            for (int j = 0; j < 4; j++) {
                dhh[q * 4 + j] = shh[q * 4 + j];
                dhl[q * 4 + j] = shl[q * 4 + j];
            }
        }
        __syncthreads();

        // ---- 3 passes of HMMA over this K chunk ----
        #pragma unroll
        for (int pass = 0; pass < 3; pass++) {
            const __nv_bfloat16* Ap = (pass == 2) ? Alo : Ahi;
            const __nv_bfloat16* Bp = (pass == 1) ? Blo : Bhi;
            #pragma unroll
            for (int kk = 0; kk < 64; kk += 16) {
                unsigned a[2][4], b[4][2];
                #pragma unroll
                for (int mt = 0; mt < 2; mt++) {
                    const __nv_bfloat16* p = Ap + aoff + mt * 16 * PA + kk;
                    a[mt][0] = *(const unsigned*)(p);
                    a[mt][1] = *(const unsigned*)(p + 8 * PA);
                    a[mt][2] = *(const unsigned*)(p + 8);
                    a[mt][3] = *(const unsigned*)(p + 8 * PA + 8);
                }
                #pragma unroll
                for (int nt = 0; nt < 4; nt++) {
                    const __nv_bfloat16* p = Bp + boff + nt * 8 * PA + kk;
                    b[nt][0] = *(const unsigned*)(p);
                    b[nt][1] = *(const unsigned*)(p + 8);
                }
                #pragma unroll
                for (int mt = 0; mt < 2; mt++)
                    #pragma unroll
                    for (int nt = 0; nt < 4; nt++)
                        asm volatile(
                            "mma.sync.aligned.m16n8k16.row.col.f32.bf16.bf16.f32 "
                            "{%0,%1,%2,%3}, {%4,%5,%6,%7}, {%8,%9}, {%0,%1,%2,%3};"
                            : "+f"(acc[mt][nt][0]), "+f"(acc[mt][nt][1]),
                              "+f"(acc[mt][nt][2]), "+f"(acc[mt][nt][3])
                            : "r"(a[mt][0]), "r"(a[mt][1]), "r"(a[mt][2]), "r"(a[mt][3]),
                              "r"(b[nt][0]), "r"(b[nt][1]));
            }
        }
    }

    // ---- C -> smem (fp32, pitch 66) over A region ----
    __syncthreads();
    float* Csm = (float*)(sm);                   // 128 x 66 floats = 33792 B
    #pragma unroll
    for (int mt = 0; mt < 2; mt++)
        #pragma unroll
        for (int nt = 0; nt < 4; nt++) {
            int r0 = mw * 32 + mt * 16 + (lane >> 2);
            int c = nw * 32 + nt * 8 + (lane & 3) * 2;
            *(float2*)(Csm + r0 * 66 + c) =
                make_float2(acc[mt][nt][0], acc[mt][nt][1]);
            *(float2*)(Csm + (r0 + 8) * 66 + c) =
                make_float2(acc[mt][nt][2], acc[mt][nt][3]);
        }
    __syncthreads();

    // ---- att logits (fp32) + fp16 h store ----
    {
        int r = tid >> 1, seg = tid & 1;
        int row = m_base + r;
        const float2* crow = (const float2*)(Csm + r * 66) + seg * 16;
        const float* asv = attm + seg * 32;
        const float* adv = attm + 64 + seg * 32;
        float s1 = 0.f, s2 = 0.f;
        uint4* dst = (uint4*)(g_hh + (size_t)row * 128) + head * 8 + seg * 4;
        #pragma unroll
        for (int q = 0; q < 4; q++) {
            uint4 pk;
            unsigned* pw = (unsigned*)&pk;
            #pragma unroll
            for (int j = 0; j < 4; j++) {
                float2 f = crow[q * 4 + j];
                s1 = fmaf(f.x, asv[q * 8 + j * 2], s1);
                s1 = fmaf(f.y, asv[q * 8 + j * 2 + 1], s1);
                s2 = fmaf(f.x, adv[q * 8 + j * 2], s2);
                s2 = fmaf(f.y, adv[q * 8 + j * 2 + 1], s2);
                __half2 hv = __floats2half2_rn(f.x, f.y);
                pw[j] = *reinterpret_cast<unsigned*>(&hv);
            }
            dst[q] = pk;
        }
        s1 += __shfl_xor_sync(0xffffffffu, s1, 1);
        s2 += __shfl_xor_sync(0xffffffffu, s2, 1);
        if (seg == 0 && row < N) {
            ((float*)&g_asrc[row])[head] = s1;
            ((float*)&g_adst[row])[head] = s2;
        }
    }
}

// ---------------- 5: three-phase exclusive scan ----------------
__global__ void scan_a_kernel(int N) {
    __shared__ int sh[256];
    int idx = blockIdx.x * 256 + threadIdx.x;
    int v = (idx < N) ? g_cnt[idx] : 0;
    sh[threadIdx.x] = v;
    __syncthreads();
    #pragma unroll
    for (int off = 128; off >= 1; off >>= 1) {
        if (threadIdx.x < off) sh[threadIdx.x] += sh[threadIdx.x + off];
        __syncthreads();
    }
    if (threadIdx.x == 0) g_bsum[blockIdx.x] = sh[0];
}

__global__ void scan_b_kernel(int GB) {
    __shared__ int sh[256];
    int t = threadIdx.x;
    int v = (t < GB) ? g_bsum[t] : 0;
    sh[t] = v;
    __syncthreads();
    #pragma unroll
    for (int off = 1; off < 256; off <<= 1) {
        int u = (t >= off) ? sh[t - off] : 0;
        __syncthreads();
        sh[t] += u;
        __syncthreads();
    }
    g_boff[t] = sh[t] - v;
}

__global__ void scan_c_kernel(int N, int ET) {
    __shared__ int sh[256];
    int t = threadIdx.x;
    int idx = blockIdx.x * 256 + t;
    int c = (idx < N) ? g_cnt[idx] : 0;
    sh[t] = c;
    __syncthreads();
    #pragma unroll
    for (int off = 1; off < 256; off <<= 1) {
        int u = (t >= off) ? sh[t - off] : 0;
        __syncthreads();
        sh[t] += u;
        __syncthreads();
    }
    int ex = g_boff[blockIdx.x] + sh[t] - c;
    if (idx < N) {
        g_off[idx] = ex;
        g_cur[idx] = ex;
        if (idx == N - 1) g_off[N] = ET;
    }
}

// ---------------- 6: scatter (CSR fill) ----------------
__global__ void scatter_kernel(const unsigned* __restrict__ w, int E, int N) {
    __shared__ int s_st;
    if (threadIdx.x == 0) s_st = edge_stride(w);
    __syncthreads();
    int st = s_st;
    int i = blockIdx.x * blockDim.x + threadIdx.x;
    if (i >= E + N) return;
    int s, d;
    if (i < E) {
        s = (int)w[st * i];
        d = (int)w[st * E + st * i];
    } else {
        s = d = i - E;
    }
    int pos = atomicAdd(&g_cur[d], 1);
    g_src[pos] = s;
}

// ---------------- 7: fused softmax + aggregate + bias + mix-ELU ------------
__device__ __forceinline__ float mixelu(float z) {
    float e = z > 0.0f ? z : expm1f(z);
    return 0.5f * z + 0.5f * e;
}

__global__ void __launch_bounds__(256)
agg_kernel(float* __restrict__ out, const float* __restrict__ bias, int N) {
    int gt = blockIdx.x * blockDim.x + threadIdx.x;
    int d = gt >> 5;
    int lane = gt & 31;
    if (d >= N) return;
    int beg = g_off[d], end = g_off[d + 1];
    int head = lane >> 3;                        // 8 features per lane
    bool hsel = (head & 1) != 0;
    bool hhi = head >= 2;

    float4 ad4 = g_adst[d];
    float ad = hhi ? (hsel ? ad4.w : ad4.z) : (hsel ? ad4.y : ad4.x);

    float acc[8] = {0.f, 0.f, 0.f, 0.f, 0.f, 0.f, 0.f, 0.f};
    float se = 0.f;

    #pragma unroll 2
    for (int j = beg; j < end; j++) {
        int s = __ldg(&g_src[j]);
        float4 as4 = __ldg(&g_asrc[s]);
        float as = hhi ? (hsel ? as4.w : as4.z) : (hsel ? as4.y : as4.x);
        float e = __expf(lrelu(as + ad));
        se += e;
        uint4 u = __ldg((const uint4*)(g_hh + (size_t)s * 128) + lane);
        float2 p0 = __half22float2(*reinterpret_cast<__half2*>(&u.x));
        float2 p1 = __half22float2(*reinterpret_cast<__half2*>(&u.y));
        float2 p2 = __half22float2(*reinterpret_cast<__half2*>(&u.z));
        float2 p3 = __half22float2(*reinterpret_cast<__half2*>(&u.w));
        acc[0] = fmaf(e, p0.x, acc[0]); acc[1] = fmaf(e, p0.y, acc[1]);
        acc[2] = fmaf(e, p1.x, acc[2]); acc[3] = fmaf(e, p1.y, acc[3]);
        acc[4] = fmaf(e, p2.x, acc[4]); acc[5] = fmaf(e, p2.y, acc[5]);
        acc[6] = fmaf(e, p3.x, acc[6]); acc[7] = fmaf(e, p3.y, acc[7]);
    }

    float inv = 1.0f / (se + 1e-16f);
    const float* brow = bias + lane * 8;
    float o[8];
    #pragma unroll
    for (int c = 0; c < 8; c++)
        o[c] = mixelu(acc[c] * inv + __ldg(brow + c));

    float4* orow = (float4*)(out + (size_t)d * FTOT);
    orow[lane * 2]     = make_float4(o[0], o[1], o[2], o[3]);
    orow[lane * 2 + 1] = make_float4(o[4], o[5], o[6], o[7]);
}

// ---------------- launch ----------------
extern "C" void kernel_launch(void* const* d_in, const int* in_sizes, int n_in,
                              void* d_out, int out_size) {
    const float*    x       = (const float*)d_in[0];
    const unsigned* edge    = (const unsigned*)d_in[1];
    const float*    W       = (const float*)d_in[2];
    const float*    att_src = (const float*)d_in[3];
    const float*    att_dst = (const float*)d_in[4];
    const float*    bias    = (const float*)d_in[5];
    float*          out     = (float*)d_out;

    const int N = in_sizes[0] / IN_DIM;        // 50000
    const int E = in_sizes[1] / 2;             // 800000
    const int ET = E + N;
    const int GB = (N + 255) / 256;

    cudaFuncSetAttribute(gemm_kernel,
                         cudaFuncAttributeMaxDynamicSharedMemorySize, SMEM_BYTES);

    zero_cnt_kernel<<<(N + 255) / 256, 256>>>(N);                     // 1
    hist_kernel<<<(ET + 255) / 256, 256>>>(edge, E, N);               // 2
    wt_kernel<<<128, 256>>>(W);                                       // 3
    {
        dim3 grid((N + 127) / 128, HEADS);
        gemm_kernel<<<grid, 256, SMEM_BYTES>>>(x, att_src, att_dst, N); // 4 (profiled)
    }
    scan_a_kernel<<<GB, 256>>>(N);                                    // 5
    scan_b_kernel<<<1, 256>>>(GB);                                    // 6
    scan_c_kernel<<<GB, 256>>>(N, ET);                                // 7
    scatter_kernel<<<(ET + 255) / 256, 256>>>(edge, E, N);            // 8
    agg_kernel<<<((long)N * 32 + 255) / 256, 256>>>(out, bias, N);    // 9
}